// round 12
// baseline (speedup 1.0000x reference)
#include <cuda_runtime.h>

#define THREADS 256
#define TB 16
#define XBUF 32768
#define WBYTES 131072
#define SMEM_BYTES (WBYTES + 2 * XBUF)   // 196608

typedef unsigned long long ull;

__device__ __forceinline__ ull pk2(float lo, float hi) {
    ull r;
    asm("mov.b64 %0, {%1, %2};" : "=l"(r) : "f"(lo), "f"(hi));
    return r;
}
__device__ __forceinline__ void unpk(ull v, float& lo, float& hi) {
    asm("mov.b64 {%0, %1}, %2;" : "=f"(lo), "=f"(hi) : "l"(v));
}
__device__ __forceinline__ ull ffma2(ull a, ull b, ull c) {
    ull d;
    asm("fma.rn.f32x2 %0, %1, %2, %3;" : "=l"(d) : "l"(a), "l"(b), "l"(c));
    return d;
}

// ---------------------------------------------------------------------------
// x tile layout (32KB per tile): element (b, m, h) -> byte offset
//   (b>>3)<<14 | m<<8 | ((b&7)>>2)<<7 | (b&1)<<6 | slot<<4
//   slot = ((((b&7)>>1)&1)<<1 | h) ^ (m&3)
// Reader (bhalf = warp>>2, v = lane>>4, i = 0..3, b = bhalf*8 + v + 2i):
//   addr = base(bhalf,v) + m*256 + (i>>1)*128 + ((((i&1)<<1|h)^(m&3))<<4)
//   -> all per-load offsets are compile-time immediates in an unroll-4 block,
//      and the two v-variants are 64B apart (same 128B line -> 1 wavefront).
// ---------------------------------------------------------------------------
__device__ __forceinline__ void stage_tile(const float* __restrict__ x,
                                           char* dstbase, int tile, int tid) {
    const float4* src = reinterpret_cast<const float4*>(x) + (size_t)tile * 2048;
    unsigned int dsb = (unsigned int)__cvta_generic_to_shared(dstbase);
#pragma unroll
    for (int r = 0; r < 8; r++) {
        int idx = tid + r * 256;
        int b = idx >> 7, rem = idx & 127, m = rem >> 1, h = rem & 1;
        int ii = (b & 7) >> 1, v = b & 1, bh = b >> 3;
        int slot = (((ii & 1) << 1) | h) ^ (m & 3);
        unsigned int db = (unsigned)((bh << 14) + (m << 8) + ((ii >> 1) << 7)
                                     + (v << 6) + (slot << 4));
        asm volatile("cp.async.cg.shared.global [%0], [%1], 16;\n"
                     :: "r"(dsb + db), "l"(src + idx));
    }
    asm volatile("cp.async.commit_group;\n");
}

__global__ __launch_bounds__(THREADS, 1)
void clifford_gate_kernel(const float* __restrict__ x,
                          const float* __restrict__ wp,
                          const float* __restrict__ bpr,
                          const float* __restrict__ wm,
                          const float* __restrict__ bmr,
                          float* __restrict__ out,
                          int ntiles) {
    extern __shared__ char smc[];
    float4* wsp = reinterpret_cast<float4*>(smc);        // [m*64+n] probe
    float4* wsm = wsp + 4096;                             // [m*64+n] match
    char*   xb  = smc + WBYTES;                           // 2 x 32KB tiles

    const int tid  = threadIdx.x;
    const int lane = tid & 31;
    const int warp = tid >> 5;
    const int nbase = (warp & 3) << 4;   // 4 warps cover n 0..63
    const int bhalf = warp >> 2;         // batch half 0/1
    const int nn = lane & 15;
    const int n  = nbase + nn;
    const int v  = lane >> 4;            // batch variant; b = bhalf*8 + v + 2i

    // ---- stage weights once: gmem [n][m][4] -> smem [m][n][4] ----
    {
        const float4* gp = reinterpret_cast<const float4*>(wp);
        const float4* gm = reinterpret_cast<const float4*>(wm);
        for (int idx = tid; idx < 4096; idx += THREADS) {
            int n2 = idx & 63, mm = idx >> 6;
            wsp[mm * 64 + n2] = gp[n2 * 64 + mm];
            wsm[mm * 64 + n2] = gm[n2 * 64 + mm];
        }
    }
    const float biasp = bpr[n];
    const float biasm = bmr[n];

    int t = blockIdx.x;
    const int stride = gridDim.x;
    if (t < ntiles) stage_tile(x, xb, t, tid);
    asm volatile("cp.async.wait_group 0;\n");
    __syncthreads();

    int cur = 0;
    const float s2 = 0.70710678118654752440f;
    const int xtoff = (bhalf << 14) + (v << 6);

    for (; t < ntiles; t += stride) {
        int tn = t + stride;
        if (tn < ntiles) stage_tile(x, xb + (cur ^ 1) * XBUF, tn, tid);

        // ---------------- mainloop ----------------
        // Per-blade reduction: single accumulator, m ascending, fused fma —
        // DO NOT change (bit-exact vs reference; gate/q are singular).
        ull aP[4][4], aM[4][4];
#pragma unroll
        for (int i = 0; i < 4; i++)
#pragma unroll
            for (int j = 0; j < 4; j++) { aP[i][j] = 0ull; aM[i][j] = 0ull; }

        const char* xt = xb + cur * XBUF + xtoff;

#pragma unroll 4
        for (int m = 0; m < 64; m++) {
            float4 wpv = wsp[(m << 6) + n];
            float4 wmv = wsm[(m << 6) + n];
            // SUBSPACE packs: A=(w0,w1), B=(w1,w1), C=(w2,w2), D=(w2,w3)
            ull wpA, wpD, wmA, wmD;
            {
                const ulonglong2* u = reinterpret_cast<const ulonglong2*>(&wpv);
                wpA = u->x; wpD = u->y;
                const ulonglong2* vv = reinterpret_cast<const ulonglong2*>(&wmv);
                wmA = vv->x; wmD = vv->y;
            }
            ull wpB = pk2(wpv.y, wpv.y), wpC = pk2(wpv.z, wpv.z);
            ull wmB = pk2(wmv.y, wmv.y), wmC = pk2(wmv.z, wmv.z);

            const char* xm = xt + (m << 8);
#pragma unroll
            for (int i = 0; i < 4; i++) {
                const char* bi = xm + ((i >> 1) << 7);
                const int s0 = ((((i & 1) << 1) | 0) ^ (m & 3)) << 4;
                const int s1 = ((((i & 1) << 1) | 1) ^ (m & 3)) << 4;
                ulonglong2 c0 = *reinterpret_cast<const ulonglong2*>(bi + s0);
                ulonglong2 c1 = *reinterpret_cast<const ulonglong2*>(bi + s1);
                aP[i][0] = ffma2(c0.x, wpA, aP[i][0]);   // blades 0,1
                aP[i][1] = ffma2(c0.y, wpB, aP[i][1]);   // blades 2,3
                aP[i][2] = ffma2(c1.x, wpC, aP[i][2]);   // blades 4,5
                aP[i][3] = ffma2(c1.y, wpD, aP[i][3]);   // blades 6,7
                aM[i][0] = ffma2(c0.x, wmA, aM[i][0]);
                aM[i][1] = ffma2(c0.y, wmB, aM[i][1]);
                aM[i][2] = ffma2(c1.x, wmC, aM[i][2]);
                aM[i][3] = ffma2(c1.y, wmD, aM[i][3]);
            }
        }

        // ---------------- epilogue ----------------
#pragma unroll
        for (int i = 0; i < 4; i++) {
            float p0, p1, p2, p3, p4, p5, p6, p7;
            float m0, m1, m2, m3, m4, m5, m6, m7;
            unpk(aP[i][0], p0, p1); unpk(aP[i][1], p2, p3);
            unpk(aP[i][2], p4, p5); unpk(aP[i][3], p6, p7);
            unpk(aM[i][0], m0, m1); unpk(aM[i][1], m2, m3);
            unpk(aM[i][2], m4, m5); unpk(aM[i][3], m6, m7);
            p0 = __fadd_rn(p0, biasp);
            m0 = __fadd_rn(m0, biasm);

            // gate: individually rounded multiplies + sequential adds i=0..7.
            // NO FMA here (bit-exactness near b==0 is required).
            float bgv;
            bgv = __fmul_rn(p0, m0);
            bgv = __fadd_rn(bgv, __fmul_rn(p1, m1));
            bgv = __fadd_rn(bgv, __fmul_rn(p2, m2));
            bgv = __fadd_rn(bgv, __fmul_rn(p3, m3));
            bgv = __fadd_rn(bgv, __fmul_rn(p4, m4));
            bgv = __fadd_rn(bgv, __fmul_rn(p5, m5));
            bgv = __fadd_rn(bgv, __fmul_rn(p6, m6));
            bgv = __fadd_rn(bgv, __fmul_rn(p7, m7));

            // q: same rounding discipline (singular near q==0).
            float qv;
            qv = __fmul_rn(m0, m0);
            qv = __fadd_rn(qv, __fmul_rn(m1, m1));
            qv = __fadd_rn(qv, __fmul_rn(m2, m2));
            qv = __fadd_rn(qv, __fmul_rn(m3, m3));
            qv = __fadd_rn(qv, -__fmul_rn(m4, m4));
            qv = __fadd_rn(qv, -__fmul_rn(m5, m5));
            qv = __fadd_rn(qv, -__fmul_rn(m6, m6));
            qv = __fadd_rn(qv, -__fmul_rn(m7, m7));

            float qs  = __fadd_rn(__fmul_rn(qv, qv), 1e-16f);
            float nrm = __fsqrt_rn(__fsqrt_rn(qs));
            float inv = __frcp_rn(nrm);

            float n0 = m0 * inv, n1 = m1 * inv, n2 = m2 * inv, n3 = m3 * inv;
            float n4 = m4 * inv, n5 = m5 * inv, n6 = m6 * inv, n7 = m7 * inv;

            // Cl(3,0) geometric product r = p * n (well-conditioned; fma ok)
            float r0 = p0*n0 + p1*n1 + p2*n2 + p3*n3 - p4*n4 - p5*n5 - p6*n6 - p7*n7;
            float r1 = p0*n1 + p1*n0 - p2*n4 + p4*n2 - p3*n5 + p5*n3 - p6*n7 - p7*n6;
            float r2 = p0*n2 + p2*n0 + p1*n4 - p4*n1 - p3*n6 + p6*n3 + p5*n7 + p7*n5;
            float r3 = p0*n3 + p3*n0 + p1*n5 - p5*n1 + p2*n6 - p6*n2 - p4*n7 - p7*n4;
            float r4 = p0*n4 + p4*n0 + p1*n2 - p2*n1 + p3*n7 + p7*n3 - p5*n6 + p6*n5;
            float r5 = p0*n5 + p5*n0 + p1*n3 - p3*n1 - p2*n7 - p7*n2 + p4*n6 - p6*n4;
            float r6 = p0*n6 + p6*n0 + p1*n7 + p7*n1 + p2*n3 - p3*n2 - p4*n5 + p5*n4;
            float r7 = p0*n7 + p7*n0 + p1*n6 + p6*n1 - p2*n5 - p5*n2 + p3*n4 + p4*n3;

            bool sel = bgv > 0.0f;
            float4 o0, o1;
            o0.x = (sel ? p0 : r0) * s2;
            o0.y = (sel ? p1 : r1) * s2;
            o0.z = (sel ? p2 : r2) * s2;
            o0.w = (sel ? p3 : r3) * s2;
            o1.x = (sel ? p4 : r4) * s2;
            o1.y = (sel ? p5 : r5) * s2;
            o1.z = (sel ? p6 : r6) * s2;
            o1.w = (sel ? p7 : r7) * s2;

            size_t brow = (size_t)t * TB + (size_t)(bhalf * 8 + v + 2 * i);
            float4* op = reinterpret_cast<float4*>(out + ((brow << 6) + n) * 8);
            op[0] = o0;
            op[1] = o1;
        }

        asm volatile("cp.async.wait_group 0;\n");
        __syncthreads();
        cur ^= 1;
    }
}

extern "C" void kernel_launch(void* const* d_in, const int* in_sizes, int n_in,
                              void* d_out, int out_size) {
    const float* x   = (const float*)d_in[0];
    const float* wp  = (const float*)d_in[1];
    const float* bpr = (const float*)d_in[2];
    const float* wm  = (const float*)d_in[3];
    const float* bmr = (const float*)d_in[4];
    float* out = (float*)d_out;

    int B = in_sizes[0] / 512;      // x is (B, 64, 8)
    int ntiles = B / TB;

    cudaFuncSetAttribute(clifford_gate_kernel,
                         cudaFuncAttributeMaxDynamicSharedMemorySize, SMEM_BYTES);

    int dev = 0, sms = 148;
    cudaGetDevice(&dev);
    cudaDeviceGetAttribute(&sms, cudaDevAttrMultiProcessorCount, dev);
    int grid = sms < ntiles ? sms : ntiles;
    if (grid < 1) grid = 1;

    clifford_gate_kernel<<<grid, THREADS, SMEM_BYTES>>>(
        x, wp, bpr, wm, bmr, out, ntiles);
}

// round 13
// speedup vs baseline: 1.0618x; 1.0618x over previous
#include <cuda_runtime.h>

#define THREADS 256
#define TB 16
#define XBUF 32768
#define WBYTES 131072
#define SMEM_BYTES (WBYTES + 2 * XBUF)   // 196608

typedef unsigned long long ull;

__device__ __forceinline__ ull pk2(float lo, float hi) {
    ull r;
    asm("mov.b64 %0, {%1, %2};" : "=l"(r) : "f"(lo), "f"(hi));
    return r;
}
__device__ __forceinline__ void unpk(ull v, float& lo, float& hi) {
    asm("mov.b64 {%0, %1}, %2;" : "=f"(lo), "=f"(hi) : "l"(v));
}
__device__ __forceinline__ ull ffma2(ull a, ull b, ull c) {
    ull d;
    asm("fma.rn.f32x2 %0, %1, %2, %3;" : "=l"(d) : "l"(a), "l"(b), "l"(c));
    return d;
}

// ---------------------------------------------------------------------------
// x tile layout (32KB per tile): element (b, m, h) -> byte offset
//   (b>>3)<<14 | m<<8 | ((b&7)>>2)<<7 | (b&1)<<6 | slot<<4
//   slot = ((((b&7)>>1)&1)<<1 | h) ^ (m&3)
// Reader (bhalf = warp>>2, v = lane>>4, i = 0..3, b = bhalf*8 + v + 2i):
//   addr = base(bhalf,v) + m*256 + (i>>1)*128 + ((((i&1)<<1|h)^(m&3))<<4)
//   -> slot offsets are compile-time immediates whenever m's low bits are
//      known (unrolled pipeline), and the two v-variants are 64B apart
//      (same 128B line -> 1 wavefront per x LDS.128).
// ---------------------------------------------------------------------------
__device__ __forceinline__ void stage_tile(const float* __restrict__ x,
                                           char* dstbase, int tile, int tid) {
    const float4* src = reinterpret_cast<const float4*>(x) + (size_t)tile * 2048;
    unsigned int dsb = (unsigned int)__cvta_generic_to_shared(dstbase);
#pragma unroll
    for (int r = 0; r < 8; r++) {
        int idx = tid + r * 256;
        int b = idx >> 7, rem = idx & 127, m = rem >> 1, h = rem & 1;
        int ii = (b & 7) >> 1, v = b & 1, bh = b >> 3;
        int slot = (((ii & 1) << 1) | h) ^ (m & 3);
        unsigned int db = (unsigned)((bh << 14) + (m << 8) + ((ii >> 1) << 7)
                                     + (v << 6) + (slot << 4));
        asm volatile("cp.async.cg.shared.global [%0], [%1], 16;\n"
                     :: "r"(dsb + db), "l"(src + idx));
    }
    asm volatile("cp.async.commit_group;\n");
}

// ---- pipeline stage helpers ----
__device__ __forceinline__ void ldw(const float4* __restrict__ wsp,
                                    const float4* __restrict__ wsm,
                                    int m, int n, float4& wpv, float4& wmv) {
    wpv = wsp[(m << 6) + n];
    wmv = wsm[(m << 6) + n];
}

__device__ __forceinline__ void ldx(const char* __restrict__ xt, int m,
                                    ulonglong2* c0, ulonglong2* c1) {
    const char* xm = xt + (m << 8);
#pragma unroll
    for (int i = 0; i < 4; i++) {
        const char* bi = xm + ((i >> 1) << 7);
        const int s0 = ((((i & 1) << 1) | 0) ^ (m & 3)) << 4;
        const int s1 = ((((i & 1) << 1) | 1) ^ (m & 3)) << 4;
        c0[i] = *reinterpret_cast<const ulonglong2*>(bi + s0);
        c1[i] = *reinterpret_cast<const ulonglong2*>(bi + s1);
    }
}

// one m-step of both GEMMs: per-blade single-accumulator fused-fma chains,
// m ascending — DO NOT change (bit-exact vs reference; gate/q are singular).
__device__ __forceinline__ void domma(const float4& wpv, const float4& wmv,
                                      const ulonglong2* c0, const ulonglong2* c1,
                                      ull aP[4][4], ull aM[4][4]) {
    // SUBSPACE packs: A=(w0,w1), B=(w1,w1), C=(w2,w2), D=(w2,w3)
    ull wpA, wpD, wmA, wmD;
    {
        const ulonglong2* u = reinterpret_cast<const ulonglong2*>(&wpv);
        wpA = u->x; wpD = u->y;
        const ulonglong2* v = reinterpret_cast<const ulonglong2*>(&wmv);
        wmA = v->x; wmD = v->y;
    }
    ull wpB = pk2(wpv.y, wpv.y), wpC = pk2(wpv.z, wpv.z);
    ull wmB = pk2(wmv.y, wmv.y), wmC = pk2(wmv.z, wmv.z);
#pragma unroll
    for (int i = 0; i < 4; i++) {
        aP[i][0] = ffma2(c0[i].x, wpA, aP[i][0]);   // blades 0,1
        aP[i][1] = ffma2(c0[i].y, wpB, aP[i][1]);   // blades 2,3
        aP[i][2] = ffma2(c1[i].x, wpC, aP[i][2]);   // blades 4,5
        aP[i][3] = ffma2(c1[i].y, wpD, aP[i][3]);   // blades 6,7
        aM[i][0] = ffma2(c0[i].x, wmA, aM[i][0]);
        aM[i][1] = ffma2(c0[i].y, wmB, aM[i][1]);
        aM[i][2] = ffma2(c1[i].x, wmC, aM[i][2]);
        aM[i][3] = ffma2(c1[i].y, wmD, aM[i][3]);
    }
}

__global__ __launch_bounds__(THREADS, 1)
void clifford_gate_kernel(const float* __restrict__ x,
                          const float* __restrict__ wp,
                          const float* __restrict__ bpr,
                          const float* __restrict__ wm,
                          const float* __restrict__ bmr,
                          float* __restrict__ out,
                          int ntiles) {
    extern __shared__ char smc[];
    float4* wsp = reinterpret_cast<float4*>(smc);        // [m*64+n] probe
    float4* wsm = wsp + 4096;                             // [m*64+n] match
    char*   xb  = smc + WBYTES;                           // 2 x 32KB tiles

    const int tid  = threadIdx.x;
    const int lane = tid & 31;
    const int warp = tid >> 5;
    const int nbase = (warp & 3) << 4;   // 4 warps cover n 0..63
    const int bhalf = warp >> 2;         // batch half 0/1
    const int nn = lane & 15;
    const int n  = nbase + nn;
    const int v  = lane >> 4;            // batch variant; b = bhalf*8 + v + 2i

    // ---- stage weights once: gmem [n][m][4] -> smem [m][n][4] ----
    {
        const float4* gp = reinterpret_cast<const float4*>(wp);
        const float4* gm = reinterpret_cast<const float4*>(wm);
        for (int idx = tid; idx < 4096; idx += THREADS) {
            int n2 = idx & 63, mm = idx >> 6;
            wsp[mm * 64 + n2] = gp[n2 * 64 + mm];
            wsm[mm * 64 + n2] = gm[n2 * 64 + mm];
        }
    }
    const float biasp = bpr[n];
    const float biasm = bmr[n];

    int t = blockIdx.x;
    const int stride = gridDim.x;
    if (t < ntiles) stage_tile(x, xb, t, tid);
    asm volatile("cp.async.wait_group 0;\n");
    __syncthreads();

    int cur = 0;
    const float s2 = 0.70710678118654752440f;
    const int xtoff = (bhalf << 14) + (v << 6);

    for (; t < ntiles; t += stride) {
        int tn = t + stride;
        if (tn < ntiles) stage_tile(x, xb + (cur ^ 1) * XBUF, tn, tid);

        ull aP[4][4], aM[4][4];
#pragma unroll
        for (int i = 0; i < 4; i++)
#pragma unroll
            for (int j = 0; j < 4; j++) { aP[i][j] = 0ull; aM[i][j] = 0ull; }

        const char* xt = xb + cur * XBUF + xtoff;

        // ---- software-pipelined mainloop: prefetch depth 1, ping-pong ----
        float4 wpA4, wmA4, wpB4, wmB4;
        ulonglong2 a0[4], a1[4], b0[4], b1[4];

        ldw(wsp, wsm, 0, n, wpA4, wmA4);
        ldx(xt, 0, a0, a1);

#pragma unroll 4
        for (int m = 0; m < 64; m += 2) {
            // prefetch m+1 into set B, then consume set A (m)
            ldw(wsp, wsm, m + 1, n, wpB4, wmB4);
            ldx(xt, m + 1, b0, b1);
            domma(wpA4, wmA4, a0, a1, aP, aM);
            // prefetch m+2 (wraps to 0 on last block; loaded value unused)
            int m2 = (m + 2) & 63;
            ldw(wsp, wsm, m2, n, wpA4, wmA4);
            ldx(xt, m2, a0, a1);
            domma(wpB4, wmB4, b0, b1, aP, aM);
        }

        // ---------------- epilogue ----------------
#pragma unroll
        for (int i = 0; i < 4; i++) {
            float p0, p1, p2, p3, p4, p5, p6, p7;
            float m0, m1, m2, m3, m4, m5, m6, m7;
            unpk(aP[i][0], p0, p1); unpk(aP[i][1], p2, p3);
            unpk(aP[i][2], p4, p5); unpk(aP[i][3], p6, p7);
            unpk(aM[i][0], m0, m1); unpk(aM[i][1], m2, m3);
            unpk(aM[i][2], m4, m5); unpk(aM[i][3], m6, m7);
            p0 = __fadd_rn(p0, biasp);
            m0 = __fadd_rn(m0, biasm);

            // gate: individually rounded multiplies + sequential adds i=0..7.
            // NO FMA here (bit-exactness near b==0 is required).
            float bgv;
            bgv = __fmul_rn(p0, m0);
            bgv = __fadd_rn(bgv, __fmul_rn(p1, m1));
            bgv = __fadd_rn(bgv, __fmul_rn(p2, m2));
            bgv = __fadd_rn(bgv, __fmul_rn(p3, m3));
            bgv = __fadd_rn(bgv, __fmul_rn(p4, m4));
            bgv = __fadd_rn(bgv, __fmul_rn(p5, m5));
            bgv = __fadd_rn(bgv, __fmul_rn(p6, m6));
            bgv = __fadd_rn(bgv, __fmul_rn(p7, m7));

            // q: same rounding discipline (singular near q==0).
            float qv;
            qv = __fmul_rn(m0, m0);
            qv = __fadd_rn(qv, __fmul_rn(m1, m1));
            qv = __fadd_rn(qv, __fmul_rn(m2, m2));
            qv = __fadd_rn(qv, __fmul_rn(m3, m3));
            qv = __fadd_rn(qv, -__fmul_rn(m4, m4));
            qv = __fadd_rn(qv, -__fmul_rn(m5, m5));
            qv = __fadd_rn(qv, -__fmul_rn(m6, m6));
            qv = __fadd_rn(qv, -__fmul_rn(m7, m7));

            float qs  = __fadd_rn(__fmul_rn(qv, qv), 1e-16f);
            float nrm = __fsqrt_rn(__fsqrt_rn(qs));
            float inv = __frcp_rn(nrm);

            float n0 = m0 * inv, n1 = m1 * inv, n2 = m2 * inv, n3 = m3 * inv;
            float n4 = m4 * inv, n5 = m5 * inv, n6 = m6 * inv, n7 = m7 * inv;

            // Cl(3,0) geometric product r = p * n (well-conditioned; fma ok)
            float r0 = p0*n0 + p1*n1 + p2*n2 + p3*n3 - p4*n4 - p5*n5 - p6*n6 - p7*n7;
            float r1 = p0*n1 + p1*n0 - p2*n4 + p4*n2 - p3*n5 + p5*n3 - p6*n7 - p7*n6;
            float r2 = p0*n2 + p2*n0 + p1*n4 - p4*n1 - p3*n6 + p6*n3 + p5*n7 + p7*n5;
            float r3 = p0*n3 + p3*n0 + p1*n5 - p5*n1 + p2*n6 - p6*n2 - p4*n7 - p7*n4;
            float r4 = p0*n4 + p4*n0 + p1*n2 - p2*n1 + p3*n7 + p7*n3 - p5*n6 + p6*n5;
            float r5 = p0*n5 + p5*n0 + p1*n3 - p3*n1 - p2*n7 - p7*n2 + p4*n6 - p6*n4;
            float r6 = p0*n6 + p6*n0 + p1*n7 + p7*n1 + p2*n3 - p3*n2 - p4*n5 + p5*n4;
            float r7 = p0*n7 + p7*n0 + p1*n6 + p6*n1 - p2*n5 - p5*n2 + p3*n4 + p4*n3;

            bool sel = bgv > 0.0f;
            float4 o0, o1;
            o0.x = (sel ? p0 : r0) * s2;
            o0.y = (sel ? p1 : r1) * s2;
            o0.z = (sel ? p2 : r2) * s2;
            o0.w = (sel ? p3 : r3) * s2;
            o1.x = (sel ? p4 : r4) * s2;
            o1.y = (sel ? p5 : r5) * s2;
            o1.z = (sel ? p6 : r6) * s2;
            o1.w = (sel ? p7 : r7) * s2;

            size_t brow = (size_t)t * TB + (size_t)(bhalf * 8 + v + 2 * i);
            float4* op = reinterpret_cast<float4*>(out + ((brow << 6) + n) * 8);
            op[0] = o0;
            op[1] = o1;
        }

        asm volatile("cp.async.wait_group 0;\n");
        __syncthreads();
        cur ^= 1;
    }
}

extern "C" void kernel_launch(void* const* d_in, const int* in_sizes, int n_in,
                              void* d_out, int out_size) {
    const float* x   = (const float*)d_in[0];
    const float* wp  = (const float*)d_in[1];
    const float* bpr = (const float*)d_in[2];
    const float* wm  = (const float*)d_in[3];
    const float* bmr = (const float*)d_in[4];
    float* out = (float*)d_out;

    int B = in_sizes[0] / 512;      // x is (B, 64, 8)
    int ntiles = B / TB;

    cudaFuncSetAttribute(clifford_gate_kernel,
                         cudaFuncAttributeMaxDynamicSharedMemorySize, SMEM_BYTES);

    int dev = 0, sms = 148;
    cudaGetDevice(&dev);
    cudaDeviceGetAttribute(&sms, cudaDevAttrMultiProcessorCount, dev);
    int grid = sms < ntiles ? sms : ntiles;
    if (grid < 1) grid = 1;

    clifford_gate_kernel<<<grid, THREADS, SMEM_BYTES>>>(
        x, wp, bpr, wm, bmr, out, ntiles);
}

// round 14
// speedup vs baseline: 1.1087x; 1.0443x over previous
#include <cuda_runtime.h>

#define THREADS 384
#define TB 24
#define XBUF 49152                        // 24 batches x 2048B
#define WBYTES 131072
#define SMEM_BYTES (WBYTES + 2 * XBUF)    // 229376

typedef unsigned long long ull;

__device__ __forceinline__ ull pk2(float lo, float hi) {
    ull r;
    asm("mov.b64 %0, {%1, %2};" : "=l"(r) : "f"(lo), "f"(hi));
    return r;
}
__device__ __forceinline__ void unpk(ull v, float& lo, float& hi) {
    asm("mov.b64 {%0, %1}, %2;" : "=f"(lo), "=f"(hi) : "l"(v));
}
__device__ __forceinline__ ull ffma2(ull a, ull b, ull c) {
    ull d;
    asm("fma.rn.f32x2 %0, %1, %2, %3;" : "=l"(d) : "l"(a), "l"(b), "l"(c));
    return d;
}

// stage one tile (TB=24 batches = 48KB, contiguous [b][m][8]) into smem.
// limit = total float4 count of x; out-of-range elements skipped (never read
// by a stored output).
__device__ __forceinline__ void stage_tile(const float* __restrict__ x,
                                           float* dst, long long tile, int tid,
                                           long long limit) {
    long long base = tile * 3072;
    const float4* src = reinterpret_cast<const float4*>(x) + base;
    float4* d4 = reinterpret_cast<float4*>(dst);
#pragma unroll
    for (int k = 0; k < 8; k++) {
        int i = tid + k * THREADS;
        if (base + i < limit) {
            unsigned int ds = (unsigned int)__cvta_generic_to_shared(d4 + i);
            asm volatile("cp.async.cg.shared.global [%0], [%1], 16;\n"
                         :: "r"(ds), "l"(src + i));
        }
    }
    asm volatile("cp.async.commit_group;\n");
}

// ---- pipeline stage helpers (keep loads / math separable for ptxas) ----
__device__ __forceinline__ void ldw(const float4* __restrict__ wsp,
                                    const float4* __restrict__ wsm,
                                    int m, int n, float4& wpv, float4& wmv) {
    wpv = wsp[(m << 6) + n];
    wmv = wsm[(m << 6) + n];
}

__device__ __forceinline__ void ldx(const float* __restrict__ xbc,
                                    int bg4, int m,
                                    ulonglong2* c0, ulonglong2* c1) {
#pragma unroll
    for (int bb = 0; bb < 4; bb++) {
        const ulonglong2* xp = reinterpret_cast<const ulonglong2*>(
            xbc + (((bg4 + bb) << 6) + m) * 8);
        c0[bb] = xp[0];
        c1[bb] = xp[1];
    }
}

// one m-step of both GEMMs: per-blade single-accumulator fused-fma chains,
// m ascending — DO NOT change (bit-exact vs reference; gate/q are singular).
__device__ __forceinline__ void domma(const float4& wpv, const float4& wmv,
                                      const ulonglong2* c0, const ulonglong2* c1,
                                      ull aP[4][4], ull aM[4][4]) {
    // SUBSPACE packs: A=(w0,w1), B=(w1,w1), C=(w2,w2), D=(w2,w3)
    ull wpA, wpD, wmA, wmD;
    {
        const ulonglong2* u = reinterpret_cast<const ulonglong2*>(&wpv);
        wpA = u->x; wpD = u->y;
        const ulonglong2* v = reinterpret_cast<const ulonglong2*>(&wmv);
        wmA = v->x; wmD = v->y;
    }
    ull wpB = pk2(wpv.y, wpv.y), wpC = pk2(wpv.z, wpv.z);
    ull wmB = pk2(wmv.y, wmv.y), wmC = pk2(wmv.z, wmv.z);
#pragma unroll
    for (int bb = 0; bb < 4; bb++) {
        aP[bb][0] = ffma2(c0[bb].x, wpA, aP[bb][0]);
        aP[bb][1] = ffma2(c0[bb].y, wpB, aP[bb][1]);
        aP[bb][2] = ffma2(c1[bb].x, wpC, aP[bb][2]);
        aP[bb][3] = ffma2(c1[bb].y, wpD, aP[bb][3]);
        aM[bb][0] = ffma2(c0[bb].x, wmA, aM[bb][0]);
        aM[bb][1] = ffma2(c0[bb].y, wmB, aM[bb][1]);
        aM[bb][2] = ffma2(c1[bb].x, wmC, aM[bb][2]);
        aM[bb][3] = ffma2(c1[bb].y, wmD, aM[bb][3]);
    }
}

__global__ __launch_bounds__(THREADS, 1)
void clifford_gate_kernel(const float* __restrict__ x,
                          const float* __restrict__ wp,
                          const float* __restrict__ bpr,
                          const float* __restrict__ wm,
                          const float* __restrict__ bmr,
                          float* __restrict__ out,
                          int ntiles, long long nB) {
    extern __shared__ float smf[];
    float4* wsp = reinterpret_cast<float4*>(smf);          // 4096 float4, [m*64+n]
    float4* wsm = wsp + 4096;                               // 4096 float4
    float*  xb  = smf + 32768;                              // 2 * 12288 floats

    const int tid  = threadIdx.x;
    const int lane = tid & 31;
    const int warp = tid >> 5;
    const int n    = ((warp & 1) << 5) | lane;   // 0..63
    const int bg4  = (warp >> 1) << 2;           // local b base: 0,4,...,20

    // ---- stage weights once: gmem [n][m][4] -> smem [m][n][4] ----
    {
        const float4* gp = reinterpret_cast<const float4*>(wp);
        const float4* gm = reinterpret_cast<const float4*>(wm);
        for (int idx = tid; idx < 4096; idx += THREADS) {
            int nn = idx & 63, mm = idx >> 6;
            wsp[mm * 64 + nn] = gp[nn * 64 + mm];
            wsm[mm * 64 + nn] = gm[nn * 64 + mm];
        }
    }
    const float biasp = bpr[n];
    const float biasm = bmr[n];
    const long long limit = nB * 128;   // total float4 in x

    int t = blockIdx.x;
    const int stride = gridDim.x;
    if (t < ntiles) stage_tile(x, xb, t, tid, limit);
    asm volatile("cp.async.wait_group 0;\n");
    __syncthreads();

    int cur = 0;
    const float s2 = 0.70710678118654752440f;

    for (; t < ntiles; t += stride) {
        int tn = t + stride;
        if (tn < ntiles) stage_tile(x, xb + (cur ^ 1) * 12288, tn, tid, limit);

        ull aP[4][4], aM[4][4];
#pragma unroll
        for (int i = 0; i < 4; i++)
#pragma unroll
            for (int j = 0; j < 4; j++) { aP[i][j] = 0ull; aM[i][j] = 0ull; }

        const float* xbc = xb + cur * 12288;

        // ---- software-pipelined mainloop: prefetch depth 1 m, ping-pong ----
        float4 wpA4, wmA4, wpB4, wmB4;
        ulonglong2 a0[4], a1[4], b0[4], b1[4];

        ldw(wsp, wsm, 0, n, wpA4, wmA4);
        ldx(xbc, bg4, 0, a0, a1);

#pragma unroll 4
        for (int m = 0; m < 64; m += 2) {
            // prefetch m+1 into set B, then consume set A (m)
            ldw(wsp, wsm, m + 1, n, wpB4, wmB4);
            ldx(xbc, bg4, m + 1, b0, b1);
            domma(wpA4, wmA4, a0, a1, aP, aM);
            // prefetch m+2 (wraps to 0 on last block; loaded value unused)
            int m2 = (m + 2) & 63;
            ldw(wsp, wsm, m2, n, wpA4, wmA4);
            ldx(xbc, bg4, m2, a0, a1);
            domma(wpB4, wmB4, b0, b1, aP, aM);
        }

        // ---------------- epilogue ----------------
        long long bbase = (long long)t * TB + bg4;
#pragma unroll
        for (int bb = 0; bb < 4; bb++) {
            long long brow = bbase + bb;
            if (brow >= nB) break;

            float p0, p1, p2, p3, p4, p5, p6, p7;
            float m0, m1, m2, m3, m4, m5, m6, m7;
            unpk(aP[bb][0], p0, p1); unpk(aP[bb][1], p2, p3);
            unpk(aP[bb][2], p4, p5); unpk(aP[bb][3], p6, p7);
            unpk(aM[bb][0], m0, m1); unpk(aM[bb][1], m2, m3);
            unpk(aM[bb][2], m4, m5); unpk(aM[bb][3], m6, m7);
            p0 = __fadd_rn(p0, biasp);
            m0 = __fadd_rn(m0, biasm);

            // gate: individually rounded multiplies + sequential adds i=0..7.
            // NO FMA here (bit-exactness near b==0 is required).
            float bgv;
            bgv = __fmul_rn(p0, m0);
            bgv = __fadd_rn(bgv, __fmul_rn(p1, m1));
            bgv = __fadd_rn(bgv, __fmul_rn(p2, m2));
            bgv = __fadd_rn(bgv, __fmul_rn(p3, m3));
            bgv = __fadd_rn(bgv, __fmul_rn(p4, m4));
            bgv = __fadd_rn(bgv, __fmul_rn(p5, m5));
            bgv = __fadd_rn(bgv, __fmul_rn(p6, m6));
            bgv = __fadd_rn(bgv, __fmul_rn(p7, m7));

            // q: same rounding discipline (singular near q==0).
            float qv;
            qv = __fmul_rn(m0, m0);
            qv = __fadd_rn(qv, __fmul_rn(m1, m1));
            qv = __fadd_rn(qv, __fmul_rn(m2, m2));
            qv = __fadd_rn(qv, __fmul_rn(m3, m3));
            qv = __fadd_rn(qv, -__fmul_rn(m4, m4));
            qv = __fadd_rn(qv, -__fmul_rn(m5, m5));
            qv = __fadd_rn(qv, -__fmul_rn(m6, m6));
            qv = __fadd_rn(qv, -__fmul_rn(m7, m7));

            float qs  = __fadd_rn(__fmul_rn(qv, qv), 1e-16f);
            float nrm = __fsqrt_rn(__fsqrt_rn(qs));
            float inv = __frcp_rn(nrm);

            float n0 = m0 * inv, n1 = m1 * inv, n2 = m2 * inv, n3 = m3 * inv;
            float n4 = m4 * inv, n5 = m5 * inv, n6 = m6 * inv, n7 = m7 * inv;

            // Cl(3,0) geometric product r = p * n (well-conditioned; fma ok)
            float r0 = p0*n0 + p1*n1 + p2*n2 + p3*n3 - p4*n4 - p5*n5 - p6*n6 - p7*n7;
            float r1 = p0*n1 + p1*n0 - p2*n4 + p4*n2 - p3*n5 + p5*n3 - p6*n7 - p7*n6;
            float r2 = p0*n2 + p2*n0 + p1*n4 - p4*n1 - p3*n6 + p6*n3 + p5*n7 + p7*n5;
            float r3 = p0*n3 + p3*n0 + p1*n5 - p5*n1 + p2*n6 - p6*n2 - p4*n7 - p7*n4;
            float r4 = p0*n4 + p4*n0 + p1*n2 - p2*n1 + p3*n7 + p7*n3 - p5*n6 + p6*n5;
            float r5 = p0*n5 + p5*n0 + p1*n3 - p3*n1 - p2*n7 - p7*n2 + p4*n6 - p6*n4;
            float r6 = p0*n6 + p6*n0 + p1*n7 + p7*n1 + p2*n3 - p3*n2 - p4*n5 + p5*n4;
            float r7 = p0*n7 + p7*n0 + p1*n6 + p6*n1 - p2*n5 - p5*n2 + p3*n4 + p4*n3;

            bool sel = bgv > 0.0f;
            float4 o0, o1;
            o0.x = (sel ? p0 : r0) * s2;
            o0.y = (sel ? p1 : r1) * s2;
            o0.z = (sel ? p2 : r2) * s2;
            o0.w = (sel ? p3 : r3) * s2;
            o1.x = (sel ? p4 : r4) * s2;
            o1.y = (sel ? p5 : r5) * s2;
            o1.z = (sel ? p6 : r6) * s2;
            o1.w = (sel ? p7 : r7) * s2;

            float4* op = reinterpret_cast<float4*>(out + ((brow << 6) + n) * 8);
            op[0] = o0;
            op[1] = o1;
        }

        asm volatile("cp.async.wait_group 0;\n");
        __syncthreads();
        cur ^= 1;
    }
}

extern "C" void kernel_launch(void* const* d_in, const int* in_sizes, int n_in,
                              void* d_out, int out_size) {
    const float* x   = (const float*)d_in[0];
    const float* wp  = (const float*)d_in[1];
    const float* bpr = (const float*)d_in[2];
    const float* wm  = (const float*)d_in[3];
    const float* bmr = (const float*)d_in[4];
    float* out = (float*)d_out;

    long long B = in_sizes[0] / 512;           // x is (B, 64, 8)
    int ntiles = (int)((B + TB - 1) / TB);

    cudaFuncSetAttribute(clifford_gate_kernel,
                         cudaFuncAttributeMaxDynamicSharedMemorySize, SMEM_BYTES);

    int dev = 0, sms = 148;
    cudaGetDevice(&dev);
    cudaDeviceGetAttribute(&sms, cudaDevAttrMultiProcessorCount, dev);
    int grid = sms < ntiles ? sms : ntiles;
    if (grid < 1) grid = 1;

    clifford_gate_kernel<<<grid, THREADS, SMEM_BYTES>>>(
        x, wp, bpr, wm, bmr, out, ntiles, B);
}